// round 11
// baseline (speedup 1.0000x reference)
#include <cuda_runtime.h>
#include <cuda_fp16.h>
#include <cstdint>
#include <cstddef>

#define BDIM 64
#define TDIM 512
#define DDIM 512
#define HDIM 1024
#define ODIM 512
#define G3   3072
#define MROWS 32768            // B*T
#define RCTA 64                // recurrence CTAs (single wave)
#define RJ   16                // hidden units per recurrence CTA

// Scratch (device globals are the sanctioned no-alloc workaround)
__device__ float g_xall[(size_t)MROWS * G3];        // x projection, 402 MB
__device__ unsigned g_hfrag16[2][BDIM * HDIM / 2];  // h ping-pong (fp16, A-frag-major)
__device__ int g_sync[512];                         // [i*32] grp cnt i<8; [256] root; [320] flag

__device__ __forceinline__ unsigned f2tf32(float x) {
    unsigned r;
    asm("cvt.rna.tf32.f32 %0, %1;" : "=r"(r) : "f"(x));
    return r;
}

__device__ __forceinline__ unsigned packh2(float a, float b) {
    __half2 h = __floats2half2_rn(a, b);
    return *(unsigned*)&h;
}

__device__ __forceinline__ int ld_acq(const int* p) {
    int v;
    asm volatile("ld.global.acquire.gpu.s32 %0, [%1];" : "=r"(v) : "l"(p) : "memory");
    return v;
}

__device__ __forceinline__ void mma_tf32_k8(float* d,
    unsigned a0, unsigned a1, unsigned a2, unsigned a3,
    unsigned b0, unsigned b1)
{
    asm volatile(
        "mma.sync.aligned.m16n8k8.row.col.f32.tf32.tf32.f32 "
        "{%0,%1,%2,%3}, {%4,%5,%6,%7}, {%8,%9}, {%0,%1,%2,%3};\n"
        : "+f"(d[0]), "+f"(d[1]), "+f"(d[2]), "+f"(d[3])
        : "r"(a0), "r"(a1), "r"(a2), "r"(a3), "r"(b0), "r"(b1));
}

__device__ __forceinline__ void mma_f16_k16(float* d,
    unsigned a0, unsigned a1, unsigned a2, unsigned a3,
    unsigned b0, unsigned b1)
{
    asm volatile(
        "mma.sync.aligned.m16n8k16.row.col.f32.f16.f16.f32 "
        "{%0,%1,%2,%3}, {%4,%5,%6,%7}, {%8,%9}, {%0,%1,%2,%3};\n"
        : "+f"(d[0]), "+f"(d[1]), "+f"(d[2]), "+f"(d[3])
        : "r"(a0), "r"(a1), "r"(a2), "r"(a3), "r"(b0), "r"(b1));
}

__device__ __forceinline__ float sigmoidf_(float x) {
    return 1.0f / (1.0f + __expf(-x));
}
__device__ __forceinline__ float tanhf_(float x) {
    x = fminf(fmaxf(x, -15.0f), 15.0f);
    float e = __expf(-2.0f * x);
    return (1.0f - e) / (1.0f + e);
}

// One dummy launch keeps the recurrence kernel at ncu's -s 5 -c 1 slot.
__global__ void dummy_kernel() {}

// ---------------------------------------------------------------------------
// Generic NT GEMM: C[M,N] = A[M,K](rm) * B[N,K](rm)^T + bias[N]  (unchanged)
// ---------------------------------------------------------------------------
__global__ __launch_bounds__(256) void gemm_nt_kernel(
    const float* __restrict__ A, const float* __restrict__ B,
    const float* __restrict__ bias, float* __restrict__ C,
    int N, int K)
{
    __shared__ unsigned As[32][132];
    __shared__ unsigned Bs[32][132];
    const int tid  = threadIdx.x;
    const int lane = tid & 31;
    const int warp = tid >> 5;
    const int wm = warp & 3;
    const int wn = warp >> 2;
    const int g = lane >> 2;
    const int c = lane & 3;
    const int bm = blockIdx.y, bn = blockIdx.x;
    const float* Ab = A + (size_t)bm * 128 * K;
    const float* Bb = B + (size_t)bn * 128 * K;

    float acc[2][8][4];
#pragma unroll
    for (int i = 0; i < 2; i++)
#pragma unroll
        for (int j = 0; j < 8; j++)
#pragma unroll
            for (int e = 0; e < 4; e++) acc[i][j][e] = 0.0f;

    for (int k0 = 0; k0 < K; k0 += 32) {
        __syncthreads();
#pragma unroll
        for (int p = 0; p < 4; p++) {
            int flat = p * 256 + tid;
            int row = flat >> 3;
            int ks = (flat & 7) * 4;
            float4 va = *(const float4*)(Ab + (size_t)row * K + k0 + ks);
            As[ks + 0][row] = f2tf32(va.x);
            As[ks + 1][row] = f2tf32(va.y);
            As[ks + 2][row] = f2tf32(va.z);
            As[ks + 3][row] = f2tf32(va.w);
            float4 vb = *(const float4*)(Bb + (size_t)row * K + k0 + ks);
            Bs[ks + 0][row] = f2tf32(vb.x);
            Bs[ks + 1][row] = f2tf32(vb.y);
            Bs[ks + 2][row] = f2tf32(vb.z);
            Bs[ks + 3][row] = f2tf32(vb.w);
        }
        __syncthreads();
#pragma unroll
        for (int ks = 0; ks < 32; ks += 8) {
            unsigned a[2][4], b[8][2];
#pragma unroll
            for (int mt = 0; mt < 2; mt++) {
                int mb = wm * 32 + mt * 16;
                a[mt][0] = As[ks + c][mb + g];
                a[mt][1] = As[ks + c][mb + g + 8];
                a[mt][2] = As[ks + c + 4][mb + g];
                a[mt][3] = As[ks + c + 4][mb + g + 8];
            }
#pragma unroll
            for (int nt = 0; nt < 8; nt++) {
                int col = wn * 64 + nt * 8 + g;
                b[nt][0] = Bs[ks + c][col];
                b[nt][1] = Bs[ks + c + 4][col];
            }
#pragma unroll
            for (int mt = 0; mt < 2; mt++)
#pragma unroll
                for (int nt = 0; nt < 8; nt++)
                    mma_tf32_k8(acc[mt][nt], a[mt][0], a[mt][1], a[mt][2], a[mt][3],
                                b[nt][0], b[nt][1]);
        }
    }

#pragma unroll
    for (int mt = 0; mt < 2; mt++) {
        int row = bm * 128 + wm * 32 + mt * 16 + g;
#pragma unroll
        for (int nt = 0; nt < 8; nt++) {
            int col = bn * 128 + wn * 64 + nt * 8 + 2 * c;
            float b0 = bias[col], b1 = bias[col + 1];
            C[(size_t)row * N + col]           = acc[mt][nt][0] + b0;
            C[(size_t)row * N + col + 1]       = acc[mt][nt][1] + b1;
            C[(size_t)(row + 8) * N + col]     = acc[mt][nt][2] + b0;
            C[(size_t)(row + 8) * N + col + 1] = acc[mt][nt][3] + b1;
        }
    }
}

// ---------------------------------------------------------------------------
// Persistent GRU recurrence, fp16 / fp32-acc (R8 skeleton + m-paired warps +
// tree barrier). 64 CTAs, 256 threads (8 warps): mt = warp&1 (a 32-row batch
// half: m-tiles 2mt, 2mt+1), kh = warp>>1 (K quarter, 16 k16-iters). Each
// B-frag LDS.64 now feeds 2 MMAs (both m-tiles) -> SMEM crossbar bytes/step
// halved vs R8. 4-way K reduction via stride-25 SMEM. Two epilogue warps
// (kh==0). Barrier: 8-group arrival tree -> root -> release flag.
// ---------------------------------------------------------------------------
extern __shared__ unsigned rec_smem[];   // Whs16[24576 u32] + red[9600 floats]

__global__ __launch_bounds__(256, 1) void gru_rec_kernel(
    const float* __restrict__ Wh, const float* __restrict__ bh,
    float* __restrict__ hiddens)
{
    unsigned* Whs = rec_smem;                       // [kb64][gate3][jh2][lane32][2]
    float* red = (float*)(rec_smem + 24576);        // [(kh-1)*4 + mt*2 + ml][lane][25]
    const int tid  = threadIdx.x;
    const int lane = tid & 31;
    const int warp = tid >> 5;
    const int mt = warp & 1;        // batch half (m-tiles 2mt, 2mt+1)
    const int kh = warp >> 1;       // K quarter (0..3)
    const int g = lane >> 2, c = lane & 3;
    const int bid = blockIdx.x;
    const int j0 = bid * RJ;

    // Load Wh slice -> SMEM in fp16 B-fragment order, once (layout as R8).
    for (int flat = tid; flat < 64 * 6 * 32; flat += 256) {
        int kb = flat / 192, rem = flat % 192;
        int gi = rem >> 6;
        int jh = (rem >> 5) & 1;
        int ln = rem & 31;
        int gg = ln >> 2, cc = ln & 3;
        const float* wp = Wh + (size_t)(gi * HDIM + j0 + jh * 8 + gg) * HDIM + kb * 16 + 2 * cc;
        Whs[flat * 2 + 0] = packh2(wp[0], wp[1]);
        Whs[flat * 2 + 1] = packh2(wp[8], wp[9]);
    }

    float bhv[3][2][2];
#pragma unroll
    for (int gi = 0; gi < 3; gi++)
#pragma unroll
        for (int jh = 0; jh < 2; jh++) {
            int jj = j0 + jh * 8 + 2 * c;
            bhv[gi][jh][0] = bh[gi * HDIM + jj];
            bhv[gi][jh][1] = bh[gi * HDIM + jj + 1];
        }

    // Epilogue-warp persistent state. Epi warp mt owns rows mt*32 .. mt*32+31:
    // per ml (0/1): rows r0 = mt*32 + ml*16 + g and r0+8.
    float2 xv[2][3][2][2];      // [ml][gate][jh][rowhalf]
    float hpr[2][2][4];         // [ml][jh][e]
#pragma unroll
    for (int ml = 0; ml < 2; ml++)
#pragma unroll
        for (int jh = 0; jh < 2; jh++)
#pragma unroll
            for (int e = 0; e < 4; e++) hpr[ml][jh][e] = 0.0f;

    if (kh == 0) {
#pragma unroll
        for (int ml = 0; ml < 2; ml++) {
            int r0 = mt * 32 + ml * 16 + g;
#pragma unroll
            for (int gi = 0; gi < 3; gi++)
#pragma unroll
                for (int jh = 0; jh < 2; jh++) {
                    int jj = j0 + jh * 8 + 2 * c;
                    xv[ml][gi][jh][0] = *(const float2*)&g_xall[((size_t)r0 * TDIM) * G3 + gi * HDIM + jj];
                    xv[ml][gi][jh][1] = *(const float2*)&g_xall[((size_t)(r0 + 8) * TDIM) * G3 + gi * HDIM + jj];
                }
        }
    }

    __syncthreads();

    for (int t = 0; t < TDIM; t++) {
        const int pp = t & 1;

        float acc[3][2][2][4];          // [gate][jh][ml][e]
#pragma unroll
        for (int gi = 0; gi < 3; gi++)
#pragma unroll
            for (int jh = 0; jh < 2; jh++)
#pragma unroll
                for (int ml = 0; ml < 2; ml++)
#pragma unroll
                    for (int e = 0; e < 4; e++) acc[gi][jh][ml][e] = 0.0f;

        // A-frag streams for m-tiles 2mt, 2mt+1; kb = kh*16 + it.
        // addr(kb, mtile) = ((kb*4 + mtile)*32 + lane) * 4 u32.
        const unsigned* hf0 = g_hfrag16[pp] + (((kh * 16) * 4 + 2 * mt) * 32 + lane) * 4;
        const unsigned* hf1 = hf0 + 128;    // mtile +1
        // per-kb stride = 4*32*4 = 512 u32
        uint4 ring[2][4];
#pragma unroll
        for (int i = 0; i < 4; i++) {
            ring[0][i] = __ldcg((const uint4*)(hf0 + i * 512));
            ring[1][i] = __ldcg((const uint4*)(hf1 + i * 512));
        }

#pragma unroll
        for (int base = 0; base < 16; base += 4) {
#pragma unroll
            for (int u = 0; u < 4; u++) {
                const int it = base + u;
                uint4 aA = ring[0][u];
                uint4 aB = ring[1][u];
                if (it < 12) {
                    ring[0][u] = __ldcg((const uint4*)(hf0 + (it + 4) * 512));
                    ring[1][u] = __ldcg((const uint4*)(hf1 + (it + 4) * 512));
                }
                const int kb = kh * 16 + it;
                const unsigned* wk = Whs + kb * 384 + lane * 2;
#pragma unroll
                for (int gi = 0; gi < 3; gi++)
#pragma unroll
                    for (int jh = 0; jh < 2; jh++) {
                        uint2 b = *(const uint2*)(wk + (gi * 2 + jh) * 64);
                        mma_f16_k16(acc[gi][jh][0], aA.x, aA.y, aA.z, aA.w, b.x, b.y);
                        mma_f16_k16(acc[gi][jh][1], aB.x, aB.y, aB.z, aB.w, b.x, b.y);
                    }
            }
        }

        // 4-way K reduction via SMEM (stride-25 rows, conflict-free).
        if (kh) {
#pragma unroll
            for (int ml = 0; ml < 2; ml++) {
                float* rp = red + ((((kh - 1) * 2 + mt) * 2 + ml) * 32 + lane) * 25;
#pragma unroll
                for (int gi = 0; gi < 3; gi++)
#pragma unroll
                    for (int jh = 0; jh < 2; jh++)
#pragma unroll
                        for (int e = 0; e < 4; e++) rp[gi * 8 + jh * 4 + e] = acc[gi][jh][ml][e];
            }
        }
        __syncthreads();

        float hy[2][2][4];              // [ml][jh][e]
        if (kh == 0) {
            // fan-in 3 K-slots
#pragma unroll
            for (int s = 0; s < 3; s++)
#pragma unroll
                for (int ml = 0; ml < 2; ml++) {
                    const float* rp = red + (((s * 2 + mt) * 2 + ml) * 32 + lane) * 25;
#pragma unroll
                    for (int gi = 0; gi < 3; gi++)
#pragma unroll
                        for (int jh = 0; jh < 2; jh++)
#pragma unroll
                            for (int e = 0; e < 4; e++)
                                acc[gi][jh][ml][e] += rp[gi * 8 + jh * 4 + e];
                }
#pragma unroll
            for (int ml = 0; ml < 2; ml++) {
#pragma unroll
                for (int jh = 0; jh < 2; jh++)
#pragma unroll
                    for (int e = 0; e < 4; e++) {
                        int part = e & 1, row = e >> 1;
                        float pr = acc[0][jh][ml][e] + bhv[0][jh][part];
                        float pu = acc[1][jh][ml][e] + bhv[1][jh][part];
                        float pn = acc[2][jh][ml][e] + bhv[2][jh][part];
                        float xr = part ? xv[ml][0][jh][row].y : xv[ml][0][jh][row].x;
                        float xu = part ? xv[ml][1][jh][row].y : xv[ml][1][jh][row].x;
                        float xn = part ? xv[ml][2][jh][row].y : xv[ml][2][jh][row].x;
                        float rg = sigmoidf_(xr + pr);
                        float ug = sigmoidf_(xu + pu);
                        float ng = tanhf_(xn + rg * pn);
                        hy[ml][jh][e] = ug * hpr[ml][jh][e] + (1.0f - ug) * ng;
                        hpr[ml][jh][e] = hy[ml][jh][e];
                    }
                // Publish fp16 A-frag slice for m-tile 2mt+ml (one STG.128).
                uint4 w;
                w.x = packh2(hy[ml][0][0], hy[ml][0][1]);
                w.y = packh2(hy[ml][0][2], hy[ml][0][3]);
                w.z = packh2(hy[ml][1][0], hy[ml][1][1]);
                w.w = packh2(hy[ml][1][2], hy[ml][1][3]);
                unsigned* nf = g_hfrag16[pp ^ 1] + (((bid * 4 + 2 * mt + ml) * 32 + lane) << 2);
                *(uint4*)nf = w;
            }
            // Order both epilogue warps' STGs before arrive.
            asm volatile("bar.sync 1, 64;" ::: "memory");
        }

        const int target = t + 1;
        if (tid == 0) {
            __threadfence();
            // two-level arrival tree: group (bid>>3) then root, then flag.
            int o1 = atomicAdd(&g_sync[(bid >> 3) * 32], 1);
            if (o1 == target * 8 - 1) {
                int oR = atomicAdd(&g_sync[256], 1);
                if (oR == target * 8 - 1)
                    asm volatile("st.global.release.gpu.s32 [%0], %1;"
                                 :: "l"(&g_sync[320]), "r"(target) : "memory");
            }
        }

        // Hidden behind the barrier wait: hiddens output + next-x prefetch.
        if (kh == 0) {
#pragma unroll
            for (int ml = 0; ml < 2; ml++) {
                int r0 = mt * 32 + ml * 16 + g;
#pragma unroll
                for (int jh = 0; jh < 2; jh++) {
                    int jj = j0 + jh * 8 + 2 * c;
                    *(float2*)&hiddens[((size_t)r0 * TDIM + t) * HDIM + jj] =
                        make_float2(hy[ml][jh][0], hy[ml][jh][1]);
                    *(float2*)&hiddens[((size_t)(r0 + 8) * TDIM + t) * HDIM + jj] =
                        make_float2(hy[ml][jh][2], hy[ml][jh][3]);
                }
                if (t + 1 < TDIM) {
#pragma unroll
                    for (int gi = 0; gi < 3; gi++)
#pragma unroll
                        for (int jh = 0; jh < 2; jh++) {
                            int jj = j0 + jh * 8 + 2 * c;
                            xv[ml][gi][jh][0] = *(const float2*)&g_xall[((size_t)r0 * TDIM + t + 1) * G3 + gi * HDIM + jj];
                            xv[ml][gi][jh][1] = *(const float2*)&g_xall[((size_t)(r0 + 8) * TDIM + t + 1) * G3 + gi * HDIM + jj];
                        }
                }
            }
        }

        if (tid == 0) {
            int v;
            for (;;) {
                v = ld_acq(&g_sync[320]);
                if (v >= target) break;
                __nanosleep(20);
            }
        }
        __syncthreads();
    }
}

__global__ void rec_init_kernel() {
    int i = blockIdx.x * blockDim.x + threadIdx.x;
    if (i < 512) g_sync[i] = 0;
    if (i < BDIM * HDIM / 2) g_hfrag16[0][i] = 0u;
}

extern "C" void kernel_launch(void* const* d_in, const int* in_sizes, int n_in,
                              void* d_out, int out_size)
{
    (void)in_sizes; (void)n_in; (void)out_size;
    const float* inputs = (const float*)d_in[0];
    const float* Wx = (const float*)d_in[1];
    const float* bx = (const float*)d_in[2];
    const float* Wh = (const float*)d_in[3];
    const float* bh = (const float*)d_in[4];
    const float* Wo = (const float*)d_in[5];
    const float* bo = (const float*)d_in[6];

    float* hiddens = (float*)d_out;                       // (B,T,H)
    float* proj    = hiddens + (size_t)MROWS * HDIM;      // (B,T,O)

    float* xall = nullptr;
    cudaGetSymbolAddress((void**)&xall, g_xall);

    // ncu alignment (harness pre-injects 2 launches; REC lands at -s 5 -c 1)
    dummy_kernel<<<1, 32>>>();

    // Phase 0: reset flags + zero h0 fragments (every launch/replay)
    rec_init_kernel<<<256, 256>>>();

    // Phase 1: x_all = inputs @ Wx^T + bx   (M=32768, N=3072, K=512)
    gemm_nt_kernel<<<dim3(G3 / 128, MROWS / 128), 256>>>(inputs, Wx, bx, xall, G3, DDIM);

    // Phase 2: persistent GRU recurrence -> hiddens (in d_out)
    const int rec_smem_bytes = 24576 * 4 + 9600 * 4;      // 136,704 B
    cudaFuncSetAttribute(gru_rec_kernel, cudaFuncAttributeMaxDynamicSharedMemorySize, rec_smem_bytes);
    gru_rec_kernel<<<RCTA, 256, rec_smem_bytes>>>(Wh, bh, hiddens);

    // Phase 3: out = hiddens @ Wo^T + bo   (M=32768, N=512, K=1024)
    gemm_nt_kernel<<<dim3(ODIM / 128, MROWS / 128), 256>>>(hiddens, Wo, bo, proj, ODIM, HDIM);
}

// round 13
// speedup vs baseline: 2.0289x; 2.0289x over previous
#include <cuda_runtime.h>
#include <cuda_fp16.h>
#include <cstdint>
#include <cstddef>

#define BDIM 64
#define TDIM 512
#define DDIM 512
#define HDIM 1024
#define ODIM 512
#define G3   3072
#define MROWS 32768            // B*T
#define RCTA 128               // recurrence CTAs (single wave, 128 <= 148)
#define RJ   8                 // hidden units per recurrence CTA

// Scratch (device globals are the sanctioned no-alloc workaround)
__device__ float g_xall[(size_t)MROWS * G3];        // x projection, 402 MB
__device__ unsigned g_hfrag16[2][BDIM * HDIM / 2];  // h ping-pong (fp16, A-frag-major)
__device__ int g_count;                             // barrier arrivals
__device__ int g_flag;                              // barrier epoch flag

__device__ __forceinline__ unsigned f2tf32(float x) {
    unsigned r;
    asm("cvt.rna.tf32.f32 %0, %1;" : "=r"(r) : "f"(x));
    return r;
}

__device__ __forceinline__ unsigned packh2(float a, float b) {
    __half2 h = __floats2half2_rn(a, b);
    return *(unsigned*)&h;
}

__device__ __forceinline__ int ld_acq(const int* p) {
    int v;
    asm volatile("ld.global.acquire.gpu.s32 %0, [%1];" : "=r"(v) : "l"(p) : "memory");
    return v;
}

__device__ __forceinline__ void mma_tf32_k8(float* d,
    unsigned a0, unsigned a1, unsigned a2, unsigned a3,
    unsigned b0, unsigned b1)
{
    asm volatile(
        "mma.sync.aligned.m16n8k8.row.col.f32.tf32.tf32.f32 "
        "{%0,%1,%2,%3}, {%4,%5,%6,%7}, {%8,%9}, {%0,%1,%2,%3};\n"
        : "+f"(d[0]), "+f"(d[1]), "+f"(d[2]), "+f"(d[3])
        : "r"(a0), "r"(a1), "r"(a2), "r"(a3), "r"(b0), "r"(b1));
}

__device__ __forceinline__ void mma_f16_k16(float* d,
    unsigned a0, unsigned a1, unsigned a2, unsigned a3,
    unsigned b0, unsigned b1)
{
    asm volatile(
        "mma.sync.aligned.m16n8k16.row.col.f32.f16.f16.f32 "
        "{%0,%1,%2,%3}, {%4,%5,%6,%7}, {%8,%9}, {%0,%1,%2,%3};\n"
        : "+f"(d[0]), "+f"(d[1]), "+f"(d[2]), "+f"(d[3])
        : "r"(a0), "r"(a1), "r"(a2), "r"(a3), "r"(b0), "r"(b1));
}

__device__ __forceinline__ float sigmoidf_(float x) {
    return 1.0f / (1.0f + __expf(-x));
}
__device__ __forceinline__ float tanhf_(float x) {
    x = fminf(fmaxf(x, -15.0f), 15.0f);
    float e = __expf(-2.0f * x);
    return (1.0f - e) / (1.0f + e);
}

// One dummy launch keeps the recurrence kernel at ncu's -s 5 -c 1 slot.
__global__ void dummy_kernel() {}

// ---------------------------------------------------------------------------
// Generic NT GEMM: C[M,N] = A[M,K](rm) * B[N,K](rm)^T + bias[N]  (unchanged)
// ---------------------------------------------------------------------------
__global__ __launch_bounds__(256) void gemm_nt_kernel(
    const float* __restrict__ A, const float* __restrict__ B,
    const float* __restrict__ bias, float* __restrict__ C,
    int N, int K)
{
    __shared__ unsigned As[32][132];
    __shared__ unsigned Bs[32][132];
    const int tid  = threadIdx.x;
    const int lane = tid & 31;
    const int warp = tid >> 5;
    const int wm = warp & 3;
    const int wn = warp >> 2;
    const int g = lane >> 2;
    const int c = lane & 3;
    const int bm = blockIdx.y, bn = blockIdx.x;
    const float* Ab = A + (size_t)bm * 128 * K;
    const float* Bb = B + (size_t)bn * 128 * K;

    float acc[2][8][4];
#pragma unroll
    for (int i = 0; i < 2; i++)
#pragma unroll
        for (int j = 0; j < 8; j++)
#pragma unroll
            for (int e = 0; e < 4; e++) acc[i][j][e] = 0.0f;

    for (int k0 = 0; k0 < K; k0 += 32) {
        __syncthreads();
#pragma unroll
        for (int p = 0; p < 4; p++) {
            int flat = p * 256 + tid;
            int row = flat >> 3;
            int ks = (flat & 7) * 4;
            float4 va = *(const float4*)(Ab + (size_t)row * K + k0 + ks);
            As[ks + 0][row] = f2tf32(va.x);
            As[ks + 1][row] = f2tf32(va.y);
            As[ks + 2][row] = f2tf32(va.z);
            As[ks + 3][row] = f2tf32(va.w);
            float4 vb = *(const float4*)(Bb + (size_t)row * K + k0 + ks);
            Bs[ks + 0][row] = f2tf32(vb.x);
            Bs[ks + 1][row] = f2tf32(vb.y);
            Bs[ks + 2][row] = f2tf32(vb.z);
            Bs[ks + 3][row] = f2tf32(vb.w);
        }
        __syncthreads();
#pragma unroll
        for (int ks = 0; ks < 32; ks += 8) {
            unsigned a[2][4], b[8][2];
#pragma unroll
            for (int mt = 0; mt < 2; mt++) {
                int mb = wm * 32 + mt * 16;
                a[mt][0] = As[ks + c][mb + g];
                a[mt][1] = As[ks + c][mb + g + 8];
                a[mt][2] = As[ks + c + 4][mb + g];
                a[mt][3] = As[ks + c + 4][mb + g + 8];
            }
#pragma unroll
            for (int nt = 0; nt < 8; nt++) {
                int col = wn * 64 + nt * 8 + g;
                b[nt][0] = Bs[ks + c][col];
                b[nt][1] = Bs[ks + c + 4][col];
            }
#pragma unroll
            for (int mt = 0; mt < 2; mt++)
#pragma unroll
                for (int nt = 0; nt < 8; nt++)
                    mma_tf32_k8(acc[mt][nt], a[mt][0], a[mt][1], a[mt][2], a[mt][3],
                                b[nt][0], b[nt][1]);
        }
    }

#pragma unroll
    for (int mt = 0; mt < 2; mt++) {
        int row = bm * 128 + wm * 32 + mt * 16 + g;
#pragma unroll
        for (int nt = 0; nt < 8; nt++) {
            int col = bn * 128 + wn * 64 + nt * 8 + 2 * c;
            float b0 = bias[col], b1 = bias[col + 1];
            C[(size_t)row * N + col]           = acc[mt][nt][0] + b0;
            C[(size_t)row * N + col + 1]       = acc[mt][nt][1] + b1;
            C[(size_t)(row + 8) * N + col]     = acc[mt][nt][2] + b0;
            C[(size_t)(row + 8) * N + col + 1] = acc[mt][nt][3] + b1;
        }
    }
}

// ---------------------------------------------------------------------------
// Persistent GRU recurrence, fp16 / fp32-acc (R8 skeleton spread over 128
// CTAs, RJ=8). 128 CTAs (single wave), 256 threads (8 warps): mt = warp&3
// (16 batch rows), kh = warp>>2 (K half, 32 k16-iters). Per iter: one a-frag
// LDG.128 (.cg, 8-deep register ring) + 3 MMAs m16n8k16 (one n8 tile per
// gate). Wh SMEM-resident fp16 B-frags (48KB). Single 2-way K reduction.
// h_prev in epilogue registers; each CTA publishes HALF a kb-slot (one
// STG.64 per epilogue thread; kbt = bid>>1, regs (bid&1)*2..+1). Flat
// count+flag barrier (128 arrivals); hiddens STG + next-x prefetch hidden
// behind the wait. A-frag consumer layout byte-identical to R8.
// ---------------------------------------------------------------------------
extern __shared__ unsigned rec_smem[];   // Whs16[12288 u32] + red[1664 floats]

__global__ __launch_bounds__(256, 1) void gru_rec_kernel(
    const float* __restrict__ Wh, const float* __restrict__ bh,
    float* __restrict__ hiddens)
{
    unsigned* Whs = rec_smem;                       // [kb64][gate3][lane32][2]
    float* red = (float*)(rec_smem + 12288);        // [mt4*lane32][13]
    const int tid  = threadIdx.x;
    const int lane = tid & 31;
    const int warp = tid >> 5;
    const int mt = warp & 3;        // batch quarter (16 rows)
    const int kh = warp >> 2;       // K half (0..1)
    const int g = lane >> 2, c = lane & 3;
    const int bid = blockIdx.x;
    const int j0 = bid * RJ;

    // Load Wh slice -> SMEM in fp16 B-fragment order, once.
    // b0 = {W[n][16kb+2cc], W[n][16kb+2cc+1]}, b1 = same +8;  n = j0+gg.
    for (int flat = tid; flat < 64 * 3 * 32; flat += 256) {
        int kb = flat / 96, rem = flat % 96;
        int gi = rem >> 5;            // gate
        int ln = rem & 31;
        int gg = ln >> 2, cc = ln & 3;
        const float* wp = Wh + (size_t)(gi * HDIM + j0 + gg) * HDIM + kb * 16 + 2 * cc;
        Whs[flat * 2 + 0] = packh2(wp[0], wp[1]);
        Whs[flat * 2 + 1] = packh2(wp[8], wp[9]);
    }

    const int jj = j0 + 2 * c;
    const int b0r = mt * 16 + g, b1r = b0r + 8;
    float bhv[3][2];                  // [gate][part]
#pragma unroll
    for (int gi = 0; gi < 3; gi++) {
        bhv[gi][0] = bh[gi * HDIM + jj];
        bhv[gi][1] = bh[gi * HDIM + jj + 1];
    }

    // Epilogue-warp persistent state: x_t prefetch and h_prev registers.
    float2 xv[3][2];
    float hpr[4];
#pragma unroll
    for (int e = 0; e < 4; e++) hpr[e] = 0.0f;
    if (kh == 0) {
#pragma unroll
        for (int gi = 0; gi < 3; gi++) {
            xv[gi][0] = *(const float2*)&g_xall[((size_t)b0r * TDIM) * G3 + gi * HDIM + jj];
            xv[gi][1] = *(const float2*)&g_xall[((size_t)b1r * TDIM) * G3 + gi * HDIM + jj];
        }
    }

    __syncthreads();

    for (int t = 0; t < TDIM; t++) {
        const int pp = t & 1;

        float acc[3][4];
#pragma unroll
        for (int gi = 0; gi < 3; gi++)
#pragma unroll
            for (int e = 0; e < 4; e++) acc[gi][e] = 0.0f;

        // A-frag stream: kb = kh*32 + it; word addr = ((kb*4+mt)*32+lane)*4.
        // 8-deep register ring (prefetch distance 8 covers L2 latency).
        const unsigned* hfp = g_hfrag16[pp] + kh * 16384 + ((mt * 32 + lane) << 2);
        uint4 ring[8];
#pragma unroll
        for (int i = 0; i < 8; i++)
            ring[i] = __ldcg((const uint4*)(hfp + i * 512));

        for (int base = 0; base < 32; base += 8) {
#pragma unroll
            for (int u = 0; u < 8; u++) {
                const int it = base + u;
                uint4 a = ring[u];
                if (it < 24)
                    ring[u] = __ldcg((const uint4*)(hfp + (it + 8) * 512));
                const int kb = kh * 32 + it;
                const unsigned* wk = Whs + kb * 192 + lane * 2;
#pragma unroll
                for (int gi = 0; gi < 3; gi++) {
                    uint2 b = *(const uint2*)(wk + gi * 64);
                    mma_f16_k16(acc[gi], a.x, a.y, a.z, a.w, b.x, b.y);
                }
            }
        }

        // 2-way K reduction via SMEM (stride-13 float rows, conflict-free).
        if (kh == 1) {
            float* rp = red + (mt * 32 + lane) * 13;
#pragma unroll
            for (int gi = 0; gi < 3; gi++)
#pragma unroll
                for (int e = 0; e < 4; e++) rp[gi * 4 + e] = acc[gi][e];
        }
        __syncthreads();

        float hy[4];
        if (kh == 0) {
            const float* rp = red + (mt * 32 + lane) * 13;
#pragma unroll
            for (int e = 0; e < 4; e++) {
                int part = e & 1, row = e >> 1;
                float pr = acc[0][e] + rp[0 * 4 + e] + bhv[0][part];
                float pu = acc[1][e] + rp[1 * 4 + e] + bhv[1][part];
                float pn = acc[2][e] + rp[2 * 4 + e] + bhv[2][part];
                float xr = part ? xv[0][row].y : xv[0][row].x;
                float xu = part ? xv[1][row].y : xv[1][row].x;
                float xn = part ? xv[2][row].y : xv[2][row].x;
                float rg = sigmoidf_(xr + pr);
                float ug = sigmoidf_(xu + pu);
                float ng = tanhf_(xn + rg * pn);
                hy[e] = ug * hpr[e] + (1.0f - ug) * ng;
                hpr[e] = hy[e];
            }
            // fp16 A-frag publish: this CTA owns HALF of kb-slot kbt=bid>>1.
            // reg (bid&1)*2   = (row g,   k-pos 2c..2c+1 of this half)
            // reg (bid&1)*2+1 = (row g+8, same k-pos)  -> one STG.64.
            const int kbt = bid >> 1;
            const int ro = (bid & 1) * 2;
            unsigned* nf = g_hfrag16[pp ^ 1] + (((kbt * 4 + mt) * 32 + lane) << 2) + ro;
            *(uint2*)nf = make_uint2(packh2(hy[0], hy[1]), packh2(hy[2], hy[3]));
            // Order all 4 epilogue warps' STGs before arrive.
            asm volatile("bar.sync 1, 128;" ::: "memory");
        }

        const int target = t + 1;
        if (tid == 0) {
            __threadfence();
            int old = atomicAdd(&g_count, 1);
            if (old == target * RCTA - 1)
                asm volatile("st.global.release.gpu.s32 [%0], %1;"
                             :: "l"(&g_flag), "r"(target) : "memory");
        }

        // Hidden behind the barrier wait: hiddens output + next-x prefetch.
        if (kh == 0) {
            *(float2*)&hiddens[((size_t)b0r * TDIM + t) * HDIM + jj] =
                make_float2(hy[0], hy[1]);
            *(float2*)&hiddens[((size_t)b1r * TDIM + t) * HDIM + jj] =
                make_float2(hy[2], hy[3]);
            if (t + 1 < TDIM) {
#pragma unroll
                for (int gi = 0; gi < 3; gi++) {
                    xv[gi][0] = *(const float2*)&g_xall[((size_t)b0r * TDIM + t + 1) * G3 + gi * HDIM + jj];
                    xv[gi][1] = *(const float2*)&g_xall[((size_t)b1r * TDIM + t + 1) * G3 + gi * HDIM + jj];
                }
            }
        }

        if (tid == 0) {
            while (ld_acq(&g_flag) < target) __nanosleep(20);
        }
        __syncthreads();
    }
}

__global__ void rec_init_kernel() {
    int i = blockIdx.x * blockDim.x + threadIdx.x;
    if (i == 0) { g_count = 0; g_flag = 0; }
    if (i < BDIM * HDIM / 2) g_hfrag16[0][i] = 0u;
}

extern "C" void kernel_launch(void* const* d_in, const int* in_sizes, int n_in,
                              void* d_out, int out_size)
{
    (void)in_sizes; (void)n_in; (void)out_size;
    const float* inputs = (const float*)d_in[0];
    const float* Wx = (const float*)d_in[1];
    const float* bx = (const float*)d_in[2];
    const float* Wh = (const float*)d_in[3];
    const float* bh = (const float*)d_in[4];
    const float* Wo = (const float*)d_in[5];
    const float* bo = (const float*)d_in[6];

    float* hiddens = (float*)d_out;                       // (B,T,H)
    float* proj    = hiddens + (size_t)MROWS * HDIM;      // (B,T,O)

    float* xall = nullptr;
    cudaGetSymbolAddress((void**)&xall, g_xall);

    // ncu alignment (harness pre-injects 2 launches; REC lands at -s 5 -c 1)
    dummy_kernel<<<1, 32>>>();

    // Phase 0: reset flags + zero h0 fragments (every launch/replay)
    rec_init_kernel<<<256, 256>>>();

    // Phase 1: x_all = inputs @ Wx^T + bx   (M=32768, N=3072, K=512)
    gemm_nt_kernel<<<dim3(G3 / 128, MROWS / 128), 256>>>(inputs, Wx, bx, xall, G3, DDIM);

    // Phase 2: persistent GRU recurrence -> hiddens (in d_out)
    const int rec_smem_bytes = 12288 * 4 + 1664 * 4;      // 55,808 B
    cudaFuncSetAttribute(gru_rec_kernel, cudaFuncAttributeMaxDynamicSharedMemorySize, rec_smem_bytes);
    gru_rec_kernel<<<RCTA, 256, rec_smem_bytes>>>(Wh, bh, hiddens);

    // Phase 3: out = hiddens @ Wo^T + bo   (M=32768, N=512, K=1024)
    gemm_nt_kernel<<<dim3(ODIM / 128, MROWS / 128), 256>>>(hiddens, Wo, bo, proj, ODIM, HDIM);
}